// round 9
// baseline (speedup 1.0000x reference)
#include <cuda_runtime.h>
#include <cstdint>

// out[i,j] = swap_mask[i,j] ? x[i, perm[i,j]] : x[i,j]
// B=16384 rows, F=2048 cols (mask is int32).
// Key insight: x is READ-ONLY, so the row-local gather can read x directly
// through L1 (row lines are resident from this CTA's own streaming loads).
// No SMEM, no barrier. Gather LDGs predicated on mask (~10% of lanes).
// .cs streaming on perm/mask/out; default policy on x (reused by gather).

#define N_FEAT   2048
#define THREADS  256

__global__ __launch_bounds__(THREADS, 8)
void swap_corruption_kernel(const float* __restrict__ x,
                            const int* __restrict__ mask,
                            const int* __restrict__ perm,
                            float* __restrict__ out)
{
    const long long base = (long long)blockIdx.x * N_FEAT;

    const float*  __restrict__ xrow = x + base;
    const float4* __restrict__ x4 = reinterpret_cast<const float4*>(xrow);
    const int4*   __restrict__ p4 = reinterpret_cast<const int4*>(perm + base);
    const int4*   __restrict__ m4 = reinterpret_cast<const int4*>(mask + base);
    float4*       __restrict__ o4 = reinterpret_cast<float4*>(out + base);

    const int v0 = threadIdx.x;
    const int v1 = THREADS + threadIdx.x;

    // Front-batch the streaming loads (max MLP).
    // x: default policy (lines reused by the gather below).
    const float4 xa = x4[v0];
    const float4 xb = x4[v1];
    const int4   m0 = __ldcs(&m4[v0]);
    const int4   m1 = __ldcs(&m4[v1]);
    const int4   p0 = __ldcs(&p4[v0]);
    const int4   p1 = __ldcs(&p4[v1]);

    // Identity defaults; predicated gathers (only mask-true lanes issue LDG,
    // hitting L1 on the row lines just streamed in).
    float4 r0 = xa;
    if (m0.x) r0.x = __ldg(&xrow[p0.x]);
    if (m0.y) r0.y = __ldg(&xrow[p0.y]);
    if (m0.z) r0.z = __ldg(&xrow[p0.z]);
    if (m0.w) r0.w = __ldg(&xrow[p0.w]);

    float4 r1 = xb;
    if (m1.x) r1.x = __ldg(&xrow[p1.x]);
    if (m1.y) r1.y = __ldg(&xrow[p1.y]);
    if (m1.z) r1.z = __ldg(&xrow[p1.z]);
    if (m1.w) r1.w = __ldg(&xrow[p1.w]);

    __stcs(&o4[v0], r0);
    __stcs(&o4[v1], r1);
}

extern "C" void kernel_launch(void* const* d_in, const int* in_sizes, int n_in,
                              void* d_out, int out_size)
{
    const float* x    = (const float*)d_in[0];
    const int*   mask = (const int*)d_in[1];
    const int*   perm = (const int*)d_in[2];
    float*       out  = (float*)d_out;

    const int batch = in_sizes[0] / N_FEAT;      // 16384
    swap_corruption_kernel<<<batch, THREADS>>>(x, mask, perm, out);
}